// round 7
// baseline (speedup 1.0000x reference)
#include <cuda_runtime.h>

#define BATCH   32
#define NA      8732
#define NCLASS  91
#define NC      90
#define KTOP    400
#define NCAND   (NC * KTOP)      /* 36000 */
#define MAXDET  200
#define IMGSZ   300.0f
#define SCORE_T 0.01f
#define NMS_T   0.45f
#define BBOX_CLIP 4.135166556742356f   /* log(1000/16) */

typedef unsigned long long u64;
typedef unsigned u32;

// -------- scratch (device globals; no allocations allowed) --------
__device__ float  d_probs[(size_t)BATCH * NC * NA];      // masked fg scores, class-major
__device__ float4 d_dboxes[(size_t)BATCH * NA];          // decoded boxes (raw)
__device__ float  d_candScore[(size_t)BATCH * NCAND];    // topk masked scores
__device__ int    d_candAnchor[(size_t)BATCH * NCAND];   // topk anchor indices
__device__ float4 d_candBox[(size_t)BATCH * NCAND];      // topk boxes WITH class offset

__device__ __forceinline__ u32 fmono(float f) {
    u32 u = __float_as_uint(f);
    return u ^ ((u >> 31) ? 0xFFFFFFFFu : 0x80000000u);
}

// ================= Kernel 1: softmax (XLA:GPU warp row-reduce order) + decode
// One warp per anchor row of 91 logits. Lane l accumulates elements
// l, l+32, l+64 sequentially, then shfl_down tree (16,8,4,2,1) — replicating
// XLA:GPU's row-reduction emitter bitwise. exp = libdevice expf (XLA's).
__global__ void __launch_bounds__(1024) k_softmax_decode(
        const float* __restrict__ logits,
        const float* __restrict__ reg,
        const float* __restrict__ anchors) {
    __shared__ float s_p[NC][33];
    const float NEG_INF = __int_as_float(0xff800000);
    int w = threadIdx.x >> 5, lane = threadIdx.x & 31;
    long flat = (long)blockIdx.x * 32 + w;            // grid covers exactly BATCH*NA
    size_t lbase = (size_t)flat * NCLASS;

    float x0 = logits[lbase + lane];
    float x1 = logits[lbase + lane + 32];
    float x2 = (lane < 27) ? logits[lbase + lane + 64] : NEG_INF;

    float m = fmaxf(fmaxf(x0, x1), x2);
    #pragma unroll
    for (int o = 16; o; o >>= 1) m = fmaxf(m, __shfl_down_sync(0xffffffffu, m, o));
    m = __shfl_sync(0xffffffffu, m, 0);

    float e0 = expf(x0 - m), e1 = expf(x1 - m), e2 = expf(x2 - m);  // pad -> 0
    float s = __fadd_rn(__fadd_rn(e0, e1), e2);
    #pragma unroll
    for (int o = 16; o; o >>= 1) s = __fadd_rn(s, __shfl_down_sync(0xffffffffu, s, o));
    s = __shfl_sync(0xffffffffu, s, 0);

    if (lane >= 1) {
        float p = __fdiv_rn(e0, s);
        s_p[lane - 1][w] = (p > SCORE_T) ? p : NEG_INF;
    }
    {
        float p = __fdiv_rn(e1, s);
        s_p[lane + 31][w] = (p > SCORE_T) ? p : NEG_INF;
    }
    if (lane < 27) {
        float p = __fdiv_rn(e2, s);
        s_p[lane + 63][w] = (p > SCORE_T) ? p : NEG_INF;
    }
    __syncthreads();

    // coalesced class-major writes
    for (int i = threadIdx.x; i < NC * 32; i += 1024) {
        int c = i >> 5, wl = i & 31;
        long fl = (long)blockIdx.x * 32 + wl;
        int b = (int)(fl / NA), a = (int)(fl % NA);
        d_probs[((size_t)b * NC + c) * NA + a] = s_p[c][wl];
    }

    // decode boxes: 32 threads, one anchor each (exact IEEE, no contraction)
    if (threadIdx.x < 32) {
        long fl = (long)blockIdx.x * 32 + threadIdx.x;
        int b = (int)(fl / NA), a = (int)(fl % NA);
        float4 rg = ((const float4*)reg)[fl];
        float4 an = ((const float4*)anchors)[a];
        float wa = __fsub_rn(an.z, an.x), ha = __fsub_rn(an.w, an.y);
        float cxa = __fadd_rn(an.x, __fmul_rn(0.5f, wa));
        float cya = __fadd_rn(an.y, __fmul_rn(0.5f, ha));
        float dx = __fdiv_rn(rg.x, 10.0f), dy = __fdiv_rn(rg.y, 10.0f);
        float dw = fminf(__fdiv_rn(rg.z, 5.0f), BBOX_CLIP);
        float dh = fminf(__fdiv_rn(rg.w, 5.0f), BBOX_CLIP);
        float cx = __fadd_rn(__fmul_rn(dx, wa), cxa);
        float cy = __fadd_rn(__fmul_rn(dy, ha), cya);
        float bw = __fmul_rn(expf(dw), wa), bh = __fmul_rn(expf(dh), ha);
        float hw = __fmul_rn(0.5f, bw), hh = __fmul_rn(0.5f, bh);
        float4 bx;
        bx.x = fminf(fmaxf(__fsub_rn(cx, hw), 0.f), IMGSZ);
        bx.y = fminf(fmaxf(__fsub_rn(cy, hh), 0.f), IMGSZ);
        bx.z = fminf(fmaxf(__fadd_rn(cx, hw), 0.f), IMGSZ);
        bx.w = fminf(fmaxf(__fadd_rn(cy, hh), 0.f), IMGSZ);
        d_dboxes[(size_t)b * NA + a] = bx;
    }
}

// ================= Kernel 2: per-(b,c) top-400 =================
#define TKTHREADS 512
#define NLOC 18
#define TKCAP 2048

__global__ void __launch_bounds__(TKTHREADS) k_topk() {
    int b = blockIdx.x / NC, c = blockIdx.x % NC;
    const float* sc = &d_probs[((size_t)b * NC + c) * NA];
    int t = threadIdx.x;

    u32 key[NLOC];
    #pragma unroll
    for (int j = 0; j < NLOC; j++) {
        int idx = j * TKTHREADS + t;
        float v = (idx < NA) ? sc[idx] : -1.0f;
        key[j] = (idx < NA && v > SCORE_T) ? fmono(v) : 0u;
    }

    __shared__ int s_cnt;
    u64 lo = 1, hi = 0xFFFFFFFFull;
    u32 tau = 0;
    while (lo <= hi) {
        u32 mid = (u32)(lo + ((hi - lo) >> 1));
        if (t == 0) s_cnt = 0;
        __syncthreads();
        int cl = 0;
        #pragma unroll
        for (int j = 0; j < NLOC; j++) cl += (key[j] >= mid);
        #pragma unroll
        for (int o = 16; o; o >>= 1) cl += __shfl_down_sync(0xffffffffu, cl, o);
        if ((t & 31) == 0) atomicAdd(&s_cnt, cl);
        __syncthreads();
        int cnt = s_cnt;
        __syncthreads();
        if (cnt >= KTOP) { tau = mid; lo = (u64)mid + 1; }
        else             { hi = (u64)mid - 1; }
    }

    __shared__ u64 buf[TKCAP];
    __shared__ int s_n;
    if (t == 0) s_n = 0;
    for (int i = t; i < TKCAP; i += TKTHREADS) buf[i] = 0ull;
    __syncthreads();
    #pragma unroll
    for (int j = 0; j < NLOC; j++) {
        if (key[j] != 0u && key[j] >= tau) {
            int p = atomicAdd(&s_n, 1);
            if (p < TKCAP) {
                u32 anchor = (u32)(j * TKTHREADS + t);
                buf[p] = ((u64)key[j] << 32) | (u64)(0xFFFFFFFFu - anchor);
            }
        }
    }
    __syncthreads();

    for (int k = 2; k <= TKCAP; k <<= 1) {
        for (int j2 = k >> 1; j2 > 0; j2 >>= 1) {
            for (int i = t; i < TKCAP; i += TKTHREADS) {
                int ixj = i ^ j2;
                if (ixj > i) {
                    u64 x = buf[i], y = buf[ixj];
                    bool sw = ((i & k) == 0) ? (x < y) : (x > y);
                    if (sw) { buf[i] = y; buf[ixj] = x; }
                }
            }
            __syncthreads();
        }
    }

    int nv = min(s_n, TKCAP);
    size_t obase = (size_t)b * NCAND + c * KTOP;
    float off = __fmul_rn((float)(c + 1), IMGSZ + 1.0f);  // exact integer
    for (int r = t; r < KTOP; r += TKTHREADS) {
        float scv = -__int_as_float(0x7f800000);
        int anc = 0;
        if (r < nv) {
            u64 v = buf[r];
            u32 h32 = (u32)(v >> 32);
            scv = __uint_as_float(h32 ^ 0x80000000u);
            anc = (int)(0xFFFFFFFFu - (u32)v);
        }
        d_candScore[obase + r]  = scv;
        d_candAnchor[obase + r] = anc;
        float4 raw = d_dboxes[(size_t)b * NA + anc];
        float4 ob;
        ob.x = __fadd_rn(raw.x, off);
        ob.y = __fadd_rn(raw.y, off);
        ob.z = __fadd_rn(raw.z, off);
        ob.w = __fadd_rn(raw.w, off);
        d_candBox[obase + r] = ob;
    }
}

// ========== Kernel 3: literal global greedy NMS (reference-faithful) ==========
#define CHUNK 36   /* 36000 = 1000 * 36 */

__device__ __forceinline__ u64 chunk_key(const float* s_sc, int t) {
    u64 best = 0ull;
    int base = t * CHUNK;
    #pragma unroll
    for (int j = 0; j < CHUNK; j++) {
        int idx = base + j;
        u64 k = ((u64)fmono(s_sc[idx]) << 32) | (u64)(0xFFFFFFFFu - (u32)idx);
        if (k > best) best = k;
    }
    return best;
}

__global__ void __launch_bounds__(1024) k_nms_global(float* __restrict__ out) {
    extern __shared__ float s_sc[];           // 36000 floats = 144 KB
    __shared__ u64 s_chunk[1024];
    __shared__ u64 s_warp[32];
    __shared__ u64 s_best;
    __shared__ float4 s_bbox;
    int b = blockIdx.x, t = threadIdx.x;

    for (int i = t; i < NCAND; i += 1024)
        s_sc[i] = d_candScore[(size_t)b * NCAND + i];
    __syncthreads();
    s_chunk[t] = (t < 1000) ? chunk_key(s_sc, t) : 0ull;
    __syncthreads();

    for (int it = 0; it < MAXDET; it++) {
        u64 k = s_chunk[t];
        #pragma unroll
        for (int o = 16; o; o >>= 1) {
            u64 other = __shfl_down_sync(0xffffffffu, k, o);
            if (other > k) k = other;
        }
        if ((t & 31) == 0) s_warp[t >> 5] = k;
        __syncthreads();
        if (t < 32) {
            u64 k2 = s_warp[t];
            #pragma unroll
            for (int o = 16; o; o >>= 1) {
                u64 other = __shfl_down_sync(0xffffffffu, k2, o);
                if (other > k2) k2 = other;
            }
            if (t == 0) s_best = k2;
        }
        __syncthreads();
        u64 bk = s_best;
        int idx = (int)(0xFFFFFFFFu - (u32)bk);
        u32 hu = (u32)(bk >> 32);
        float scv = __uint_as_float((hu & 0x80000000u) ? (hu ^ 0x80000000u) : ~hu);
        bool valid = isfinite(scv);
        int cls = idx / KTOP;
        int jbase = cls * KTOP;

        float4 bx = make_float4(0.f, 0.f, 0.f, 0.f);
        if (t < KTOP) {
            bx = d_candBox[(size_t)b * NCAND + jbase + t];
            if (jbase + t == idx) s_bbox = bx;
        }
        float4 raw = make_float4(0.f, 0.f, 0.f, 0.f);
        float so = 0.f, lb = 0.f;
        if (t == 0 && valid) {
            int anc = d_candAnchor[(size_t)b * NCAND + idx];
            raw = d_dboxes[(size_t)b * NA + anc];
            so = scv;
            lb = (float)(cls + 1);
        }
        __syncthreads();

        float4 bb = s_bbox;
        if (t < KTOP) {
            float a1 = __fmul_rn(__fsub_rn(bb.z, bb.x), __fsub_rn(bb.w, bb.y));
            float a2 = __fmul_rn(__fsub_rn(bx.z, bx.x), __fsub_rn(bx.w, bx.y));
            float lx = fmaxf(bb.x, bx.x), ly = fmaxf(bb.y, bx.y);
            float rx = fminf(bb.z, bx.z), ry = fminf(bb.w, bx.w);
            float iw = fmaxf(__fsub_rn(rx, lx), 0.f);
            float ih = fmaxf(__fsub_rn(ry, ly), 0.f);
            float inter = __fmul_rn(iw, ih);
            float den = __fadd_rn(__fsub_rn(__fadd_rn(a1, a2), inter), 1e-9f);
            float iou = __fdiv_rn(inter, den);
            if (iou > NMS_T || (jbase + t) == idx)
                s_sc[jbase + t] = -__int_as_float(0x7f800000);
        }
        if (t == 0) {
            size_t ob = ((size_t)b * MAXDET + it) * 4;
            out[ob + 0] = raw.x; out[ob + 1] = raw.y;
            out[ob + 2] = raw.z; out[ob + 3] = raw.w;
            out[(size_t)BATCH * MAXDET * 4 + (size_t)b * MAXDET + it] = so;
            out[(size_t)BATCH * MAXDET * 5 + (size_t)b * MAXDET + it] = lb;
        }
        __syncthreads();

        int c0 = jbase / CHUNK;
        int c1 = (jbase + KTOP - 1) / CHUNK;
        if (t >= c0 && t <= c1) s_chunk[t] = chunk_key(s_sc, t);
        __syncthreads();
    }
}

// ================= host =================
extern "C" void kernel_launch(void* const* d_in, const int* in_sizes, int n_in,
                              void* d_out, int out_size) {
    const float* logits  = (const float*)d_in[0];
    const float* reg     = (const float*)d_in[1];
    const float* anchors = (const float*)d_in[2];
    float* out = (float*)d_out;

    k_softmax_decode<<<(BATCH * NA) / 32, 1024>>>(logits, reg, anchors);
    k_topk<<<BATCH * NC, TKTHREADS>>>();
    cudaFuncSetAttribute(k_nms_global, cudaFuncAttributeMaxDynamicSharedMemorySize,
                         NCAND * (int)sizeof(float));
    k_nms_global<<<BATCH, 1024, NCAND * sizeof(float)>>>(out);
}

// round 8
// speedup vs baseline: 1.1433x; 1.1433x over previous
#include <cuda_runtime.h>

#define BATCH   32
#define NA      8732
#define NCLASS  91
#define NC      90
#define KTOP    400
#define NCAND   (NC * KTOP)      /* 36000 */
#define MAXDET  200
#define IMGSZ   300.0f
#define SCORE_T 0.01f
#define NMS_T   0.45f
#define BBOX_CLIP 4.135166556742356f   /* log(1000/16) */

typedef unsigned long long u64;
typedef unsigned u32;

// -------- scratch (device globals; no allocations allowed) --------
__device__ float  d_probs[(size_t)BATCH * NC * NA];      // masked fg scores, class-major
__device__ float4 d_dboxes[(size_t)BATCH * NA];          // decoded boxes (raw)
__device__ float  d_candScore[(size_t)BATCH * NCAND];    // topk scores -> survivor scores
__device__ int    d_candAnchor[(size_t)BATCH * NCAND];   // topk anchor indices
__device__ float4 d_candBox[(size_t)BATCH * NCAND];      // topk boxes WITH class offset

__device__ __forceinline__ u32 fmono(float f) {
    u32 u = __float_as_uint(f);
    return u ^ ((u >> 31) ? 0xFFFFFFFFu : 0x80000000u);
}

// ================= Kernel 1: softmax (XLA:GPU warp row-reduce order) + decode
// FROZEN ARITHMETIC: bitwise-matches the reference lowering. Do not alter.
__global__ void __launch_bounds__(1024) k_softmax_decode(
        const float* __restrict__ logits,
        const float* __restrict__ reg,
        const float* __restrict__ anchors) {
    __shared__ float s_p[NC][33];
    const float NEG_INF = __int_as_float(0xff800000);
    int w = threadIdx.x >> 5, lane = threadIdx.x & 31;
    long flat = (long)blockIdx.x * 32 + w;
    size_t lbase = (size_t)flat * NCLASS;

    float x0 = logits[lbase + lane];
    float x1 = logits[lbase + lane + 32];
    float x2 = (lane < 27) ? logits[lbase + lane + 64] : NEG_INF;

    float m = fmaxf(fmaxf(x0, x1), x2);
    #pragma unroll
    for (int o = 16; o; o >>= 1) m = fmaxf(m, __shfl_down_sync(0xffffffffu, m, o));
    m = __shfl_sync(0xffffffffu, m, 0);

    float e0 = expf(x0 - m), e1 = expf(x1 - m), e2 = expf(x2 - m);
    float s = __fadd_rn(__fadd_rn(e0, e1), e2);
    #pragma unroll
    for (int o = 16; o; o >>= 1) s = __fadd_rn(s, __shfl_down_sync(0xffffffffu, s, o));
    s = __shfl_sync(0xffffffffu, s, 0);

    if (lane >= 1) {
        float p = __fdiv_rn(e0, s);
        s_p[lane - 1][w] = (p > SCORE_T) ? p : NEG_INF;
    }
    {
        float p = __fdiv_rn(e1, s);
        s_p[lane + 31][w] = (p > SCORE_T) ? p : NEG_INF;
    }
    if (lane < 27) {
        float p = __fdiv_rn(e2, s);
        s_p[lane + 63][w] = (p > SCORE_T) ? p : NEG_INF;
    }
    __syncthreads();

    for (int i = threadIdx.x; i < NC * 32; i += 1024) {
        int c = i >> 5, wl = i & 31;
        long fl = (long)blockIdx.x * 32 + wl;
        int b = (int)(fl / NA), a = (int)(fl % NA);
        d_probs[((size_t)b * NC + c) * NA + a] = s_p[c][wl];
    }

    if (threadIdx.x < 32) {
        long fl = (long)blockIdx.x * 32 + threadIdx.x;
        int b = (int)(fl / NA), a = (int)(fl % NA);
        float4 rg = ((const float4*)reg)[fl];
        float4 an = ((const float4*)anchors)[a];
        float wa = __fsub_rn(an.z, an.x), ha = __fsub_rn(an.w, an.y);
        float cxa = __fadd_rn(an.x, __fmul_rn(0.5f, wa));
        float cya = __fadd_rn(an.y, __fmul_rn(0.5f, ha));
        float dx = __fdiv_rn(rg.x, 10.0f), dy = __fdiv_rn(rg.y, 10.0f);
        float dw = fminf(__fdiv_rn(rg.z, 5.0f), BBOX_CLIP);
        float dh = fminf(__fdiv_rn(rg.w, 5.0f), BBOX_CLIP);
        float cx = __fadd_rn(__fmul_rn(dx, wa), cxa);
        float cy = __fadd_rn(__fmul_rn(dy, ha), cya);
        float bw = __fmul_rn(expf(dw), wa), bh = __fmul_rn(expf(dh), ha);
        float hw = __fmul_rn(0.5f, bw), hh = __fmul_rn(0.5f, bh);
        float4 bx;
        bx.x = fminf(fmaxf(__fsub_rn(cx, hw), 0.f), IMGSZ);
        bx.y = fminf(fmaxf(__fsub_rn(cy, hh), 0.f), IMGSZ);
        bx.z = fminf(fmaxf(__fadd_rn(cx, hw), 0.f), IMGSZ);
        bx.w = fminf(fmaxf(__fadd_rn(cy, hh), 0.f), IMGSZ);
        d_dboxes[(size_t)b * NA + a] = bx;
    }
}

// ================= Kernel 2: per-(b,c) top-400 =================
#define TKTHREADS 512
#define NLOC 18
#define TKCAP 512        /* tau = 400th value => ~400 survive; 512 covers ties */

__global__ void __launch_bounds__(TKTHREADS) k_topk() {
    int b = blockIdx.x / NC, c = blockIdx.x % NC;
    const float* sc = &d_probs[((size_t)b * NC + c) * NA];
    int t = threadIdx.x;

    u32 key[NLOC];
    #pragma unroll
    for (int j = 0; j < NLOC; j++) {
        int idx = j * TKTHREADS + t;
        float v = (idx < NA) ? sc[idx] : -1.0f;
        key[j] = (idx < NA && v > SCORE_T) ? fmono(v) : 0u;
    }

    // binary search for 400th largest key; keys live in [fmono(0.01)+1, fmono(1.0)]
    __shared__ int s_cnt;
    u64 lo = 0xBC23D70Bull, hi = 0xBF800000ull;
    u32 tau = 0;
    while (lo <= hi) {
        u32 mid = (u32)(lo + ((hi - lo) >> 1));
        if (t == 0) s_cnt = 0;
        __syncthreads();
        int cl = 0;
        #pragma unroll
        for (int j = 0; j < NLOC; j++) cl += (key[j] >= mid);
        #pragma unroll
        for (int o = 16; o; o >>= 1) cl += __shfl_down_sync(0xffffffffu, cl, o);
        if ((t & 31) == 0) atomicAdd(&s_cnt, cl);
        __syncthreads();
        int cnt = s_cnt;
        __syncthreads();
        if (cnt >= KTOP) { tau = mid; lo = (u64)mid + 1; }
        else             { hi = (u64)mid - 1; }
    }

    __shared__ u64 buf[TKCAP];
    __shared__ int s_n;
    if (t == 0) s_n = 0;
    if (t < TKCAP) buf[t] = 0ull;
    __syncthreads();
    #pragma unroll
    for (int j = 0; j < NLOC; j++) {
        if (key[j] != 0u && key[j] >= tau) {
            int p = atomicAdd(&s_n, 1);
            if (p < TKCAP) {
                u32 anchor = (u32)(j * TKTHREADS + t);
                buf[p] = ((u64)key[j] << 32) | (u64)(0xFFFFFFFFu - anchor);
            }
        }
    }
    __syncthreads();

    // bitonic sort 512 desc (score desc, anchor asc)
    for (int k = 2; k <= TKCAP; k <<= 1) {
        for (int j2 = k >> 1; j2 > 0; j2 >>= 1) {
            int i = t;
            if (i < TKCAP) {
                int ixj = i ^ j2;
                if (ixj > i) {
                    u64 x = buf[i], y = buf[ixj];
                    bool sw = ((i & k) == 0) ? (x < y) : (x > y);
                    if (sw) { buf[i] = y; buf[ixj] = x; }
                }
            }
            __syncthreads();
        }
    }

    int nv = min(s_n, TKCAP);
    size_t obase = (size_t)b * NCAND + c * KTOP;
    float off = __fmul_rn((float)(c + 1), IMGSZ + 1.0f);
    if (t < KTOP) {
        float scv = -__int_as_float(0x7f800000);
        int anc = 0;
        if (t < nv) {
            u64 v = buf[t];
            u32 h32 = (u32)(v >> 32);
            scv = __uint_as_float(h32 ^ 0x80000000u);
            anc = (int)(0xFFFFFFFFu - (u32)v);
        }
        d_candScore[obase + t]  = scv;
        d_candAnchor[obase + t] = anc;
        float4 raw = d_dboxes[(size_t)b * NA + anc];
        float4 ob;
        ob.x = __fadd_rn(raw.x, off);
        ob.y = __fadd_rn(raw.y, off);
        ob.z = __fadd_rn(raw.z, off);
        ob.w = __fadd_rn(raw.w, off);
        d_candBox[obase + t] = ob;
    }
}

// ===== Kernel 3: per-class greedy NMS (exact: cross-class IoU == 0) =====
__global__ void __launch_bounds__(416) k_nms() {
    int b = blockIdx.x / NC, c = blockIdx.x % NC;
    __shared__ float  s_sc[KTOP];
    __shared__ float4 s_bx[KTOP];
    __shared__ float  s_ar[KTOP];
    __shared__ int    s_alive[KTOP];
    int t = threadIdx.x;
    size_t base = (size_t)b * NCAND + c * KTOP;

    float4 my = make_float4(0.f, 0.f, 0.f, 0.f);
    float mya = 0.f;
    if (t < KTOP) {
        float s = d_candScore[base + t];
        float4 bx = d_candBox[base + t];
        s_sc[t] = s;
        s_bx[t] = bx;
        float ar = __fmul_rn(__fsub_rn(bx.z, bx.x), __fsub_rn(bx.w, bx.y));
        s_ar[t] = ar;
        s_alive[t] = isfinite(s) ? 1 : 0;
        my = bx; mya = ar;
    }
    __syncthreads();

    for (int i = 0; i < KTOP; i++) {
        if (s_alive[i]) {   // uniform
            if (t > i && t < KTOP && s_alive[t]) {
                float4 bi = s_bx[i];
                float lx = fmaxf(bi.x, my.x), ly = fmaxf(bi.y, my.y);
                float rx = fminf(bi.z, my.z), ry = fminf(bi.w, my.w);
                float iw = fmaxf(__fsub_rn(rx, lx), 0.f);
                float ih = fmaxf(__fsub_rn(ry, ly), 0.f);
                float inter = __fmul_rn(iw, ih);
                float den = __fadd_rn(__fsub_rn(__fadd_rn(s_ar[i], mya), inter), 1e-9f);
                float iou = __fdiv_rn(inter, den);
                if (iou > NMS_T) s_alive[t] = 0;
            }
            __syncthreads();
        }
    }
    __syncthreads();
    if (t < KTOP)
        d_candScore[base + t] = s_alive[t] ? s_sc[t] : -__int_as_float(0x7f800000);
}

// ===== Kernel 4: global top-200 of survivors by (score desc, idx asc) =====
#define SELCAP 512
#define SNLOC 36   /* ceil(36000/1024) */

__global__ void __launch_bounds__(1024) k_select(float* __restrict__ out) {
    __shared__ u64 buf[SELCAP];
    __shared__ int s_cnt, s_n;
    int b = blockIdx.x, t = threadIdx.x;

    // register-resident survivor keys
    u32 key[SNLOC];
    #pragma unroll
    for (int j = 0; j < SNLOC; j++) {
        int i = j * 1024 + t;
        if (i < NCAND) {
            float v = d_candScore[(size_t)b * NCAND + i];
            key[j] = isfinite(v) ? fmono(v) : 0u;
        } else key[j] = 0u;
    }
    if (t < SELCAP) buf[t] = 0ull;

    // binary search for the 200th largest survivor score
    u64 lo = 0xBC23D70Bull, hi = 0xBF800000ull;
    u32 tau = 0;
    while (lo <= hi) {
        u32 mid = (u32)(lo + ((hi - lo) >> 1));
        if (t == 0) s_cnt = 0;
        __syncthreads();
        int cl = 0;
        #pragma unroll
        for (int j = 0; j < SNLOC; j++) cl += (key[j] >= mid);
        #pragma unroll
        for (int o = 16; o; o >>= 1) cl += __shfl_down_sync(0xffffffffu, cl, o);
        if ((t & 31) == 0) atomicAdd(&s_cnt, cl);
        __syncthreads();
        int cnt = s_cnt;
        __syncthreads();
        if (cnt >= MAXDET) { tau = mid; lo = (u64)mid + 1; }
        else               { hi = (u64)mid - 1; }
    }
    if (t == 0) s_n = 0;
    __syncthreads();
    #pragma unroll
    for (int j = 0; j < SNLOC; j++) {
        if (key[j] != 0u && key[j] >= tau) {
            int p = atomicAdd(&s_n, 1);
            if (p < SELCAP) {
                u32 i = (u32)(j * 1024 + t);
                buf[p] = ((u64)key[j] << 32) | (u64)(0xFFFFFFFFu - i);
            }
        }
    }
    __syncthreads();

    // bitonic sort 512 desc -> exact (score desc, idx asc) order
    for (int k = 2; k <= SELCAP; k <<= 1) {
        for (int j2 = k >> 1; j2 > 0; j2 >>= 1) {
            int i = t;
            if (i < SELCAP) {
                int ixj = i ^ j2;
                if (ixj > i) {
                    u64 x = buf[i], y = buf[ixj];
                    bool sw = ((i & k) == 0) ? (x < y) : (x > y);
                    if (sw) { buf[i] = y; buf[ixj] = x; }
                }
            }
            __syncthreads();
        }
    }

    if (t < MAXDET) {
        u64 v = buf[t];
        u32 h = (u32)(v >> 32);
        float4 bx = make_float4(0.f, 0.f, 0.f, 0.f);
        float so = 0.f, lb = 0.f;
        if (h != 0u) {
            int idx = (int)(0xFFFFFFFFu - (u32)v);
            so = __uint_as_float(h ^ 0x80000000u);
            int cls = idx / KTOP;
            int anc = d_candAnchor[(size_t)b * NCAND + idx];
            bx = d_dboxes[(size_t)b * NA + anc];
            lb = (float)(cls + 1);
        }
        size_t ob = ((size_t)b * MAXDET + t) * 4;
        out[ob + 0] = bx.x; out[ob + 1] = bx.y;
        out[ob + 2] = bx.z; out[ob + 3] = bx.w;
        out[(size_t)BATCH * MAXDET * 4 + (size_t)b * MAXDET + t] = so;
        out[(size_t)BATCH * MAXDET * 5 + (size_t)b * MAXDET + t] = lb;
    }
}

// ================= host =================
extern "C" void kernel_launch(void* const* d_in, const int* in_sizes, int n_in,
                              void* d_out, int out_size) {
    const float* logits  = (const float*)d_in[0];
    const float* reg     = (const float*)d_in[1];
    const float* anchors = (const float*)d_in[2];
    float* out = (float*)d_out;

    k_softmax_decode<<<(BATCH * NA) / 32, 1024>>>(logits, reg, anchors);
    k_topk<<<BATCH * NC, TKTHREADS>>>();
    k_nms<<<BATCH * NC, 416>>>();
    k_select<<<BATCH, 1024>>>(out);
}